// round 4
// baseline (speedup 1.0000x reference)
#include <cuda_runtime.h>
#include <cstdint>

// Problem constants
#define NB    4
#define TSEQ  4096
#define CDIM  1024
#define HDIM  64
#define MROWS (NB * TSEQ)   // 16384

// Scratch for projected q, k, v  (12 MB total) — __device__ globals per alloc rules
__device__ float g_q[MROWS * HDIM];
__device__ float g_k[MROWS * HDIM];
__device__ float g_v[MROWS * HDIM];

// ---------------------------------------------------------------------------
// Projection: out[m][h] = sum_c x[m][c] * W[h][c]
// Dot-product layout: x-tile and W-tile kept [row][c] in smem (stride 36),
// vectorized float4 along c. BM=64, BN=64(=HDIM), BK=32, 256 threads.
// grid = (MROWS/64, 3); blockIdx.y selects (Wq->g_q, Wk->g_k, Wv->g_v)
// ---------------------------------------------------------------------------
#define PJ_STR 36   // 32 + 4 pad (144B rows, 16B-aligned)

__global__ __launch_bounds__(256) void proj_kernel(
    const float* __restrict__ x,
    const float* __restrict__ Wq,
    const float* __restrict__ Wk,
    const float* __restrict__ Wv)
{
    __shared__ float As[64 * PJ_STR];  // x tile   [m][c]
    __shared__ float Bs[64 * PJ_STR];  // W tile   [n][c]

    const int wsel = blockIdx.y;
    const float* __restrict__ W = (wsel == 0) ? Wq : ((wsel == 1) ? Wk : Wv);
    float* __restrict__ dst     = (wsel == 0) ? g_q : ((wsel == 1) ? g_k : g_v);

    const int m0 = blockIdx.x * 64;
    const int t  = threadIdx.x;
    const int tx = t & 15;
    const int ty = t >> 4;

    float acc[4][4] = {};

    for (int kb = 0; kb < CDIM; kb += 32) {
        #pragma unroll
        for (int p = 0; p < 2; p++) {
            const int f   = t + p * 256;
            const int row = f >> 3;
            const int c   = (f & 7) * 4;
            *(float4*)(As + row * PJ_STR + c) =
                *(const float4*)(x + (m0 + row) * CDIM + kb + c);
            *(float4*)(Bs + row * PJ_STR + c) =
                *(const float4*)(W + row * CDIM + kb + c);
        }
        __syncthreads();

        #pragma unroll
        for (int kk = 0; kk < 32; kk += 4) {
            float4 av[4], bv[4];
            #pragma unroll
            for (int ii = 0; ii < 4; ii++)
                av[ii] = *(const float4*)(As + (ty + 16 * ii) * PJ_STR + kk);
            #pragma unroll
            for (int jj = 0; jj < 4; jj++)
                bv[jj] = *(const float4*)(Bs + (tx + 16 * jj) * PJ_STR + kk);
            #pragma unroll
            for (int ii = 0; ii < 4; ii++)
                #pragma unroll
                for (int jj = 0; jj < 4; jj++) {
                    acc[ii][jj] = fmaf(av[ii].x, bv[jj].x, acc[ii][jj]);
                    acc[ii][jj] = fmaf(av[ii].y, bv[jj].y, acc[ii][jj]);
                    acc[ii][jj] = fmaf(av[ii].z, bv[jj].z, acc[ii][jj]);
                    acc[ii][jj] = fmaf(av[ii].w, bv[jj].w, acc[ii][jj]);
                }
        }
        __syncthreads();
    }

    #pragma unroll
    for (int ii = 0; ii < 4; ii++)
        #pragma unroll
        for (int jj = 0; jj < 4; jj++)
            dst[(m0 + ty + 16 * ii) * HDIM + (tx + 16 * jj)] = acc[ii][jj];
}

// ---------------------------------------------------------------------------
// Flash attention (fp32, causal). grid = (32, 4): each CTA processes the
// COMPLEMENTARY PAIR of q-tiles (63-bx, bx) -> exactly 65 k-iterations per
// CTA, perfectly balanced, placement-independent. 256 threads, 1 CTA/SM.
// K/V double-buffered via register prefetch: 2 barriers per iteration.
// Online softmax register-resident (16-lane shuffle trees).
// Smem (floats):
//   Qs [64][68]        Ks[2][64][68]      Vs[2][64][68]      St [64][65]
// ---------------------------------------------------------------------------
#define AT_STR  68
#define KV_BUF  (64 * AT_STR)               // 4352 floats per buffer
#define SM_QS   0
#define SM_KS   (64 * AT_STR)               // Ks[2] at 4352
#define SM_VS   (3 * 64 * AT_STR)           // Vs[2] at 13056
#define SM_ST   (5 * 64 * AT_STR)           // 21760
#define SM_TOTF (SM_ST + 64 * 65)           // 25920 floats
#define ATTN_SMEM_BYTES (SM_TOTF * 4)       // 103680 bytes

__global__ __launch_bounds__(256) void attn_kernel(float* __restrict__ out)
{
    extern __shared__ float sm[];
    float* Qs = sm + SM_QS;
    float* Ks = sm + SM_KS;   // Ks + cur*KV_BUF
    float* Vs = sm + SM_VS;
    float* St = sm + SM_ST;

    const int t  = threadIdx.x;
    const int tx = t & 15;
    const int ty = t >> 4;
    const int bx = blockIdx.x;            // 0..31
    const int b  = blockIdx.y;
    const float NEGBIG = -1e30f;
    const float scale  = 0.125f;          // 64^-0.5

    // row/col map for the cooperative tile loads (4 float4 per thread)
    const int lrow0 = t >> 4;             // +16 per p
    const int lcol  = (t & 15) * 4;

    const float* __restrict__ kbase = g_k + b * TSEQ * HDIM;
    const float* __restrict__ vbase = g_v + b * TSEQ * HDIM;

    #pragma unroll 1
    for (int half = 0; half < 2; half++) {
        const int qb = (half == 0) ? (63 - bx) : bx;   // heavy tile first

        // ---- load Q tile (pre-scaled) + prologue K/V(0) into buf 0 ----
        {
            const float* __restrict__ qsrc = g_q + (b * TSEQ + qb * 64) * HDIM;
            #pragma unroll
            for (int p = 0; p < 4; p++) {
                const int row = lrow0 + p * 16;
                float4 q4 = *(const float4*)(qsrc + row * HDIM + lcol);
                q4.x *= scale; q4.y *= scale; q4.z *= scale; q4.w *= scale;
                *(float4*)(Qs + row * AT_STR + lcol) = q4;
                *(float4*)(Ks + row * AT_STR + lcol) =
                    *(const float4*)(kbase + row * HDIM + lcol);
                *(float4*)(Vs + row * AT_STR + lcol) =
                    *(const float4*)(vbase + row * HDIM + lcol);
            }
        }

        float m_i[4], l_i[4];
        #pragma unroll
        for (int ii = 0; ii < 4; ii++) { m_i[ii] = NEGBIG; l_i[ii] = 0.0f; }
        float o[4][4] = {};

        __syncthreads();                               // prologue barrier

        for (int jt = 0; jt <= qb; jt++) {
            const int cur = jt & 1;
            float* __restrict__ Kc = Ks + cur * KV_BUF;
            float* __restrict__ Vc = Vs + cur * KV_BUF;

            // ---- prefetch next K/V tile into registers (latency hidden by S) ----
            float4 kpf[4], vpf[4];
            const bool pf = (jt < qb);
            if (pf) {
                const float* __restrict__ ksrc = kbase + (jt + 1) * 64 * HDIM;
                const float* __restrict__ vsrc = vbase + (jt + 1) * 64 * HDIM;
                #pragma unroll
                for (int p = 0; p < 4; p++) {
                    const int row = lrow0 + p * 16;
                    kpf[p] = *(const float4*)(ksrc + row * HDIM + lcol);
                    vpf[p] = *(const float4*)(vsrc + row * HDIM + lcol);
                }
            }

            // ---- S = (Q*scale) @ K^T ----
            float s[4][4] = {};
            #pragma unroll
            for (int kk = 0; kk < 64; kk += 4) {
                float4 av[4], bv[4];
                #pragma unroll
                for (int ii = 0; ii < 4; ii++)
                    av[ii] = *(const float4*)(Qs + (ty + 16 * ii) * AT_STR + kk);
                #pragma unroll
                for (int jj = 0; jj < 4; jj++)
                    bv[jj] = *(const float4*)(Kc + (tx + 16 * jj) * AT_STR + kk);
                #pragma unroll
                for (int ii = 0; ii < 4; ii++)
                    #pragma unroll
                    for (int jj = 0; jj < 4; jj++) {
                        s[ii][jj] = fmaf(av[ii].x, bv[jj].x, s[ii][jj]);
                        s[ii][jj] = fmaf(av[ii].y, bv[jj].y, s[ii][jj]);
                        s[ii][jj] = fmaf(av[ii].z, bv[jj].z, s[ii][jj]);
                        s[ii][jj] = fmaf(av[ii].w, bv[jj].w, s[ii][jj]);
                    }
            }

            // causal mask on the diagonal tile
            if (jt == qb) {
                #pragma unroll
                for (int ii = 0; ii < 4; ii++)
                    #pragma unroll
                    for (int jj = 0; jj < 4; jj++)
                        if ((tx + 16 * jj) > (ty + 16 * ii)) s[ii][jj] = NEGBIG;
            }

            // ---- online softmax (register-resident, 16-lane shuffle trees) ----
            float alpha[4];
            #pragma unroll
            for (int ii = 0; ii < 4; ii++) {
                float tm = fmaxf(fmaxf(s[ii][0], s[ii][1]),
                                 fmaxf(s[ii][2], s[ii][3]));
                #pragma unroll
                for (int w = 1; w < 16; w <<= 1)
                    tm = fmaxf(tm, __shfl_xor_sync(0xffffffffu, tm, w));
                const float mnew = fmaxf(m_i[ii], tm);
                alpha[ii] = __expf(m_i[ii] - mnew);
                m_i[ii]   = mnew;
            }

            #pragma unroll
            for (int ii = 0; ii < 4; ii++) {
                float p0 = __expf(s[ii][0] - m_i[ii]);
                float p1 = __expf(s[ii][1] - m_i[ii]);
                float p2 = __expf(s[ii][2] - m_i[ii]);
                float p3 = __expf(s[ii][3] - m_i[ii]);
                float rs = (p0 + p1) + (p2 + p3);
                #pragma unroll
                for (int w = 1; w < 16; w <<= 1)
                    rs += __shfl_xor_sync(0xffffffffu, rs, w);
                l_i[ii] = l_i[ii] * alpha[ii] + rs;
                o[ii][0] *= alpha[ii]; o[ii][1] *= alpha[ii];
                o[ii][2] *= alpha[ii]; o[ii][3] *= alpha[ii];
                const int i = ty + 16 * ii;
                St[(tx +  0) * 65 + i] = p0;
                St[(tx + 16) * 65 + i] = p1;
                St[(tx + 32) * 65 + i] = p2;
                St[(tx + 48) * 65 + i] = p3;
            }
            __syncthreads();                           // barrier A: St ready

            // ---- O += P @ V ----
            #pragma unroll 8
            for (int j = 0; j < 64; j++) {
                const float4 vv = *(const float4*)(Vc + j * AT_STR + tx * 4);
                float p[4];
                #pragma unroll
                for (int ii = 0; ii < 4; ii++)
                    p[ii] = St[j * 65 + ty + 16 * ii];
                #pragma unroll
                for (int ii = 0; ii < 4; ii++) {
                    o[ii][0] = fmaf(p[ii], vv.x, o[ii][0]);
                    o[ii][1] = fmaf(p[ii], vv.y, o[ii][1]);
                    o[ii][2] = fmaf(p[ii], vv.z, o[ii][2]);
                    o[ii][3] = fmaf(p[ii], vv.w, o[ii][3]);
                }
            }

            // ---- stage prefetched K/V into the alternate buffer ----
            if (pf) {
                float* __restrict__ Kn = Ks + (1 - cur) * KV_BUF;
                float* __restrict__ Vn = Vs + (1 - cur) * KV_BUF;
                #pragma unroll
                for (int p = 0; p < 4; p++) {
                    const int row = lrow0 + p * 16;
                    *(float4*)(Kn + row * AT_STR + lcol) = kpf[p];
                    *(float4*)(Vn + row * AT_STR + lcol) = vpf[p];
                }
            }
            __syncthreads();                           // barrier B: bufs/St safe
        }

        // ---- epilogue: out = O / l  (registers only; no smem hazards) ----
        #pragma unroll
        for (int ii = 0; ii < 4; ii++) {
            const int i     = ty + 16 * ii;
            const float inv = 1.0f / l_i[ii];
            float4 ov;
            ov.x = o[ii][0] * inv; ov.y = o[ii][1] * inv;
            ov.z = o[ii][2] * inv; ov.w = o[ii][3] * inv;
            *(float4*)(out + (b * TSEQ + qb * 64 + i) * HDIM + tx * 4) = ov;
        }
        // next half's Qs/Ks/Vs writes are ordered after barrier B above
    }
}

// ---------------------------------------------------------------------------
// kernel_launch — inputs (metadata order): x, mask(int32, unused), Wk, Wq, Wv
// ---------------------------------------------------------------------------
extern "C" void kernel_launch(void* const* d_in, const int* in_sizes, int n_in,
                              void* d_out, int out_size)
{
    const float* x  = (const float*)d_in[0];
    // d_in[1] = mask (int32) — causality is known; not read.
    const float* Wk = (const float*)d_in[2];
    const float* Wq = (const float*)d_in[3];
    const float* Wv = (const float*)d_in[4];
    float* out = (float*)d_out;

    // Host-side attribute set; not a stream op, safe under graph capture.
    cudaFuncSetAttribute(attn_kernel,
                         cudaFuncAttributeMaxDynamicSharedMemorySize,
                         ATTN_SMEM_BYTES);

    dim3 pgrid(MROWS / 64, 3);
    proj_kernel<<<pgrid, 256>>>(x, Wq, Wk, Wv);

    dim3 agrid(32, NB);   // paired q-tiles: uniform 65 iterations per CTA
    attn_kernel<<<agrid, 256, ATTN_SMEM_BYTES>>>(out);
}